// round 1
// baseline (speedup 1.0000x reference)
#include <cuda_runtime.h>

// Problem constants (fixed shapes)
#define B_    16
#define H_    128
#define W_    128
#define RDIM  4
#define ACT   8
#define ICH   5            // I = R+1
#define KK    45           // I*3*3 (logit/patch dim)
#define KP    48           // padded to multiple of 4 for LDS.128 / f32x2
#define NOC   (ACT*KK)     // 360 weight rows
#define SMEMW (NOC*KP)     // floats of padded W in smem (17280 -> 69120 B)

// ---- packed f32x2 helpers (Blackwell sm_103a) ----
__device__ __forceinline__ unsigned long long pack2f(float lo, float hi) {
    unsigned long long r;
    asm("mov.b64 %0, {%1, %2};" : "=l"(r) : "f"(lo), "f"(hi));
    return r;
}
__device__ __forceinline__ void unpack2f(unsigned long long v, float& lo, float& hi) {
    asm("mov.b64 {%0, %1}, %2;" : "=f"(lo), "=f"(hi) : "l"(v));
}
__device__ __forceinline__ unsigned long long ffma2(unsigned long long a,
                                                    unsigned long long b,
                                                    unsigned long long c) {
    unsigned long long d;
    asm("fma.rn.f32x2 %0, %1, %2, %3;" : "=l"(d) : "l"(a), "l"(b), "l"(c));
    return d;
}

__global__ __launch_bounds__(256, 1)
void vi_kernel(const float* __restrict__ values,
               const float* __restrict__ rewards,
               const float* __restrict__ weight,
               float* __restrict__ out)
{
    extern __shared__ float sw[];  // [360][48], rows padded 45->48 with zeros

    // Load + pad W into shared memory (W is tiny, L2-resident across blocks)
    for (int idx = threadIdx.x; idx < SMEMW; idx += 256) {
        int oc = idx / KP;
        int t  = idx - oc * KP;
        sw[idx] = (t < KK) ? __ldg(weight + oc * KK + t) : 0.0f;
    }
    __syncthreads();

    // 256 threads = 2 image rows; grid = B*H/2 = 1024 blocks
    const int lin = blockIdx.x * 2 + (threadIdx.x >> 7);  // global row id 0..2047
    const int b   = lin >> 7;
    const int h   = lin & 127;
    const int w   = threadIdx.x & 127;

    // ---- build 48-dim padded patch, packed into 24 x u64 (f32x2 pairs) ----
    float pv[KP];
#pragma unroll
    for (int t = 0; t < KP; t++) pv[t] = 0.0f;

#pragma unroll
    for (int i = 0; i < ICH; i++) {
        const float* src = (i < RDIM)
            ? rewards + (size_t)(b * RDIM + i) * (H_ * W_)
            : values  + (size_t)b * (H_ * W_);
#pragma unroll
        for (int dh = 0; dh < 3; dh++) {
            const int hh = h + dh - 1;
            const bool hok = (hh >= 0) && (hh < H_);
#pragma unroll
            for (int dw = 0; dw < 3; dw++) {
                const int ww = w + dw - 1;
                const bool ok = hok && (ww >= 0) && (ww < W_);
                pv[i * 9 + dh * 3 + dw] = ok ? __ldg(src + hh * W_ + ww) : 0.0f;
            }
        }
    }

    unsigned long long pp[KP / 2];
#pragma unroll
    for (int t2 = 0; t2 < KP / 2; t2++) pp[t2] = pack2f(pv[2 * t2], pv[2 * t2 + 1]);
    // pv is dead from here -> only pp (48 regs) stays live

    float vmax = -3.4e38f;

#pragma unroll 1
    for (int a = 0; a < ACT; a++) {
        float s = 0.0f, q = 0.0f;
        const float* wbase = sw + a * (KK * KP);

        // 45 logits in 9 groups of 5 (5 independent FFMA2 chains for ILP).
        // Logit j = dot48(patch, Wrow_j); softmax fused online (no max needed:
        // logits ~ N(0,1), exp can't overflow).
#pragma unroll
        for (int g = 0; g < 9; g++) {
            unsigned long long acc[5];
#pragma unroll
            for (int jj = 0; jj < 5; jj++) acc[jj] = 0ULL;  // (0.f, 0.f)

#pragma unroll
            for (int t4 = 0; t4 < KP / 4; t4++) {
#pragma unroll
                for (int jj = 0; jj < 5; jj++) {
                    const ulonglong2 wv = *reinterpret_cast<const ulonglong2*>(
                        wbase + (g * 5 + jj) * KP + t4 * 4);
                    acc[jj] = ffma2(pp[2 * t4],     wv.x, acc[jj]);
                    acc[jj] = ffma2(pp[2 * t4 + 1], wv.y, acc[jj]);
                }
            }
#pragma unroll
            for (int jj = 0; jj < 5; jj++) {
                const int j = g * 5 + jj;           // compile-time constant
                float lo, hi;
                unpack2f(acc[jj], lo, hi);
                const float e = __expf(lo + hi);
                float plo, phi;
                unpack2f(pp[j >> 1], plo, phi);
                const float pj = (j & 1) ? phi : plo;
                s += e;
                q = fmaf(pj, e, q);
            }
        }
        vmax = fmaxf(vmax, __fdividef(q, s));
    }

    out[((b * H_) + h) * W_ + w] = vmax;
}

extern "C" void kernel_launch(void* const* d_in, const int* in_sizes, int n_in,
                              void* d_out, int out_size)
{
    (void)in_sizes; (void)n_in; (void)out_size;
    const float* values  = (const float*)d_in[0];  // [16,128,128]
    const float* rewards = (const float*)d_in[1];  // [16,4,128,128]
    const float* weight  = (const float*)d_in[2];  // [360,5,3,3]
    float* out = (float*)d_out;                    // [16,128,128]

    const size_t smem = SMEMW * sizeof(float);     // 69120 B
    cudaFuncSetAttribute(vi_kernel, cudaFuncAttributeMaxDynamicSharedMemorySize,
                         (int)smem);

    dim3 grid(B_ * H_ / 2);   // 1024 blocks, 2 rows each
    dim3 block(256);
    vi_kernel<<<grid, block, smem>>>(values, rewards, weight, out);
}

// round 2
// speedup vs baseline: 1.1045x; 1.1045x over previous
#include <cuda_runtime.h>

// Problem constants (fixed shapes)
#define B_    16
#define H_    128
#define W_    128
#define RDIM  4
#define ACT   8
#define ICH   5            // I = R+1
#define KK    45           // I*3*3 (logit/patch dim)
#define KP    48           // row stride, padded for alignment
#define NOC   (ACT*KK)     // 360 weight rows
#define SMEMW (NOC*KP)     // floats of padded W in smem (17280 -> 69120 B)

// ---- packed f32x2 helpers (Blackwell sm_103a) ----
__device__ __forceinline__ unsigned long long pack2f(float lo, float hi) {
    unsigned long long r;
    asm("mov.b64 %0, {%1, %2};" : "=l"(r) : "f"(lo), "f"(hi));
    return r;
}
__device__ __forceinline__ void unpack2f(unsigned long long v, float& lo, float& hi) {
    asm("mov.b64 {%0, %1}, %2;" : "=f"(lo), "=f"(hi) : "l"(v));
}
__device__ __forceinline__ unsigned long long ffma2(unsigned long long a,
                                                    unsigned long long b,
                                                    unsigned long long c) {
    unsigned long long d;
    asm("fma.rn.f32x2 %0, %1, %2, %3;" : "=l"(d) : "l"(a), "l"(b), "l"(c));
    return d;
}

__global__ __launch_bounds__(256, 2)   // force regs<=128 -> 2 CTAs/SM -> 16 warps
void vi_kernel(const float* __restrict__ values,
               const float* __restrict__ rewards,
               const float* __restrict__ weight,
               float* __restrict__ out)
{
    extern __shared__ float sw[];  // [360][48], rows padded 45->48 with zeros

    // Load + pad W into shared memory (W is tiny, L2-resident across blocks)
    for (int idx = threadIdx.x; idx < SMEMW; idx += 256) {
        int oc = idx / KP;
        int t  = idx - oc * KP;
        sw[idx] = (t < KK) ? __ldg(weight + oc * KK + t) : 0.0f;
    }
    __syncthreads();

    // 256 threads = 2 image rows; grid = B*H/2 = 1024 blocks
    const int lin = blockIdx.x * 2 + (threadIdx.x >> 7);  // global row id 0..2047
    const int b   = lin >> 7;
    const int h   = lin & 127;
    const int w   = threadIdx.x & 127;

    // ---- build 46-dim padded patch (45 real + 1 zero), packed as f32x2 ----
    float pv[46];
#pragma unroll
    for (int t = 0; t < 46; t++) pv[t] = 0.0f;

#pragma unroll
    for (int i = 0; i < ICH; i++) {
        const float* src = (i < RDIM)
            ? rewards + (size_t)(b * RDIM + i) * (H_ * W_)
            : values  + (size_t)b * (H_ * W_);
#pragma unroll
        for (int dh = 0; dh < 3; dh++) {
            const int hh = h + dh - 1;
            const bool hok = (hh >= 0) && (hh < H_);
#pragma unroll
            for (int dw = 0; dw < 3; dw++) {
                const int ww = w + dw - 1;
                const bool ok = hok && (ww >= 0) && (ww < W_);
                pv[i * 9 + dh * 3 + dw] = ok ? __ldg(src + hh * W_ + ww) : 0.0f;
            }
        }
    }

    unsigned long long pp[23];   // 46 floats -> 23 f32x2 pairs
#pragma unroll
    for (int t2 = 0; t2 < 23; t2++) pp[t2] = pack2f(pv[2 * t2], pv[2 * t2 + 1]);
    // pv dead from here -> pp (46 regs) stays live

    float vmax = -3.4e38f;

#pragma unroll 1
    for (int a = 0; a < ACT; a++) {
        float s = 0.0f, q = 0.0f;
        const float* wbase = sw + a * (KK * KP);

        // 45 logits in 9 groups of 5 (5 independent FFMA2 chains for ILP).
        // Logit j = dot(patch, Wrow_j); softmax fused online (no max needed:
        // logits ~ N(0,1), exp can't overflow).
#pragma unroll
        for (int g = 0; g < 9; g++) {
            unsigned long long acc[5];
#pragma unroll
            for (int jj = 0; jj < 5; jj++) acc[jj] = 0ULL;  // (0.f, 0.f)

            // elements 0..43 via 11 x LDS.128 (2 pairs each)
#pragma unroll
            for (int t4 = 0; t4 < 11; t4++) {
#pragma unroll
                for (int jj = 0; jj < 5; jj++) {
                    const ulonglong2 wv = *reinterpret_cast<const ulonglong2*>(
                        wbase + (g * 5 + jj) * KP + t4 * 4);
                    acc[jj] = ffma2(pp[2 * t4],     wv.x, acc[jj]);
                    acc[jj] = ffma2(pp[2 * t4 + 1], wv.y, acc[jj]);
                }
            }
            // element 44 (+ zero pad 45) via 1 x LDS.64
#pragma unroll
            for (int jj = 0; jj < 5; jj++) {
                const unsigned long long wv = *reinterpret_cast<const unsigned long long*>(
                    wbase + (g * 5 + jj) * KP + 44);
                acc[jj] = ffma2(pp[22], wv, acc[jj]);
            }
#pragma unroll
            for (int jj = 0; jj < 5; jj++) {
                const int j = g * 5 + jj;           // compile-time constant
                float lo, hi;
                unpack2f(acc[jj], lo, hi);
                const float e = __expf(lo + hi);
                float plo, phi;
                unpack2f(pp[j >> 1], plo, phi);
                const float pj = (j & 1) ? phi : plo;
                s += e;
                q = fmaf(pj, e, q);
            }
        }
        vmax = fmaxf(vmax, __fdividef(q, s));
    }

    out[((b * H_) + h) * W_ + w] = vmax;
}

extern "C" void kernel_launch(void* const* d_in, const int* in_sizes, int n_in,
                              void* d_out, int out_size)
{
    (void)in_sizes; (void)n_in; (void)out_size;
    const float* values  = (const float*)d_in[0];  // [16,128,128]
    const float* rewards = (const float*)d_in[1];  // [16,4,128,128]
    const float* weight  = (const float*)d_in[2];  // [360,5,3,3]
    float* out = (float*)d_out;                    // [16,128,128]

    const size_t smem = SMEMW * sizeof(float);     // 69120 B
    cudaFuncSetAttribute(vi_kernel, cudaFuncAttributeMaxDynamicSharedMemorySize,
                         (int)smem);

    dim3 grid(B_ * H_ / 2);   // 1024 blocks, 2 rows each
    dim3 block(256);
    vi_kernel<<<grid, block, smem>>>(values, rewards, weight, out);
}